// round 16
// baseline (speedup 1.0000x reference)
#include <cuda_runtime.h>
#include <cuda_fp16.h>
#include <cstdint>

// AdaLoRALinear: out[8192,4096] = x[8192,4096] @ (W + (B*sigma_m)@A)^T
// Single-pass fp16 GEMM on mma.sync. This round: BK=128 (32 iterations,
// half the barrier/wait overhead, 8 k16-steps of MMA ILP per barrier).
// 3-stage x 64KB = 192KB/CTA -> 1 CTA/SM (occupancy proven non-binding).

#define D_DIM 4096
#define R_DIM 16
#define M_DIM 8192
#define SCALING 1.0f
#define THRESH  0.01f

#define BM 128
#define BN 128
#define BK 128                 // two 64-k sub-tiles per stage
#define KITERS (D_DIM / BK)    // 32

__device__ __half g_x16[(size_t)M_DIM * D_DIM];
__device__ __half g_w16[(size_t)D_DIM * D_DIM];

// ---------------------------------------------------------------------------
// helpers
// ---------------------------------------------------------------------------
__device__ __forceinline__ uint32_t smem_u32(const void* p) {
    uint32_t a;
    asm("{ .reg .u64 t; cvta.to.shared.u64 t, %1; cvt.u32.u64 %0, t; }"
        : "=r"(a) : "l"(p));
    return a;
}
__device__ __forceinline__ uint32_t swz128(uint32_t off) {
    return off ^ ((off >> 3) & 0x70);
}
__device__ __forceinline__ void cp16(uint32_t smem, const void* g) {
    asm volatile("cp.async.cg.shared.global [%0], [%1], 16;\n"
                 :: "r"(smem), "l"(g) : "memory");
}
__device__ __forceinline__ void cp_commit() {
    asm volatile("cp.async.commit_group;\n" ::: "memory");
}
__device__ __forceinline__ void cp_wait1() {
    asm volatile("cp.async.wait_group 1;\n" ::: "memory");
}
__device__ __forceinline__ void ldsm4(uint32_t* r, uint32_t addr) {
    asm volatile("ldmatrix.sync.aligned.m8n8.x4.shared.b16 {%0,%1,%2,%3}, [%4];"
                 : "=r"(r[0]), "=r"(r[1]), "=r"(r[2]), "=r"(r[3]) : "r"(addr));
}
__device__ __forceinline__ void mma_f16(float* d, const uint32_t* a,
                                        const uint32_t* b) {
    asm volatile(
        "mma.sync.aligned.m16n8k16.row.col.f32.f16.f16.f32 "
        "{%0,%1,%2,%3}, {%4,%5,%6,%7}, {%8,%9}, {%0,%1,%2,%3};"
        : "+f"(d[0]), "+f"(d[1]), "+f"(d[2]), "+f"(d[3])
        : "r"(a[0]), "r"(a[1]), "r"(a[2]), "r"(a[3]), "r"(b[0]), "r"(b[1]));
}

// ---------------------------------------------------------------------------
// Merged prep, parity-interleaved (round-13 best):
//   even blocks: fold W' -> fp16 (one o-row slice, 4 elems/thread)
//   odd  blocks: convert x -> fp16 (8 elems/thread)
// ---------------------------------------------------------------------------
#define PREP_BLOCKS 32768

__global__ void prep_kernel(const float* __restrict__ x,
                            const float* __restrict__ W,
                            const float* __restrict__ A,
                            const float* __restrict__ B,
                            const float* __restrict__ sigma) {
    const int bid = blockIdx.x;
    if ((bid & 1) == 0) {
        const int fb = bid >> 1;
        __shared__ float bsig[R_DIM];
        const int o = fb >> 2;
        const int i = ((fb & 3) * 256 + threadIdx.x) * 4;
        if (threadIdx.x < R_DIM) {
            float s = sigma[threadIdx.x];
            s = (fabsf(s) >= THRESH) ? s : 0.0f;
            bsig[threadIdx.x] = B[o * R_DIM + threadIdx.x] * s * SCALING;
        }
        __syncthreads();

        const size_t idx = (size_t)o * D_DIM + i;
        float4 w4 = *reinterpret_cast<const float4*>(W + idx);
        float acc[4] = {w4.x, w4.y, w4.z, w4.w};
#pragma unroll
        for (int r = 0; r < R_DIM; r++) {
            const float4 a4 =
                *reinterpret_cast<const float4*>(A + (size_t)r * D_DIM + i);
            const float b = bsig[r];
            acc[0] = fmaf(b, a4.x, acc[0]);
            acc[1] = fmaf(b, a4.y, acc[1]);
            acc[2] = fmaf(b, a4.z, acc[2]);
            acc[3] = fmaf(b, a4.w, acc[3]);
        }
        __half h[4];
#pragma unroll
        for (int j = 0; j < 4; j++) h[j] = __float2half_rn(acc[j]);
        *reinterpret_cast<uint2*>(&g_w16[idx]) = *reinterpret_cast<uint2*>(h);
    } else {
        const size_t t = (size_t)(bid >> 1) * 256 + threadIdx.x;
        const float4 v0 = reinterpret_cast<const float4*>(x)[t * 2];
        const float4 v1 = reinterpret_cast<const float4*>(x)[t * 2 + 1];
        __half h[8] = {__float2half_rn(v0.x), __float2half_rn(v0.y),
                       __float2half_rn(v0.z), __float2half_rn(v0.w),
                       __float2half_rn(v1.x), __float2half_rn(v1.y),
                       __float2half_rn(v1.z), __float2half_rn(v1.w)};
        *reinterpret_cast<uint4*>(&g_x16[t * 8]) =
            *reinterpret_cast<uint4*>(h);
    }
}

// ---------------------------------------------------------------------------
// GEMM: CTA 128x128, 256 threads, 8 warps (4m x 2n) of 32x64, BK=128,
// 3-stage pipeline (64 KB/stage) -> 192 KB/CTA -> 1 CTA/SM.
// Stage = two 64-k sub-tiles, each with the proven SW128 row layout.
// ---------------------------------------------------------------------------
#define SUB_BYTES  16384       // one 64-k sub-tile of A or B (128 rows x 128B)
#define STAGE_BYTES 65536      // A(2 subs) + B(2 subs)
#define OFF_A 0                // A subs at 0, 16384
#define OFF_B 32768            // B subs at 32768, 49152
#define SMEM_BYTES (3 * STAGE_BYTES + 128)

__device__ __forceinline__ void load_stage(uint32_t base, size_t mBase,
                                           size_t nBase, int kt, int tid) {
#pragma unroll
    for (int s = 0; s < 2; s++) {      // two 64-k sub-tiles
#pragma unroll
        for (int i = 0; i < 4; i++) {  // A sub: 128 rows x 8 units
            const int u = tid + 256 * i;
            const int row = u >> 3, kc = u & 7;
            const uint32_t so = swz128(row * 128 + kc * 16);
            cp16(base + OFF_A + s * SUB_BYTES + so,
                 g_x16 + ((mBase + row) << 12) + kt + s * 64 + kc * 8);
        }
#pragma unroll
        for (int i = 0; i < 4; i++) {  // B sub: 128 rows x 8 units
            const int u = tid + 256 * i;
            const int row = u >> 3, kc = u & 7;
            const uint32_t so = swz128(row * 128 + kc * 16);
            cp16(base + OFF_B + s * SUB_BYTES + so,
                 g_w16 + ((nBase + row) << 12) + kt + s * 64 + kc * 8);
        }
    }
}

__global__ __launch_bounds__(256, 1)
void gemm_mma_kernel(float* __restrict__ out) {
    extern __shared__ char smem_raw[];
    const uint32_t tiles = (smem_u32(smem_raw) + 127u) & ~127u;

    const int tid = threadIdx.x;
    const int lane = tid & 31;
    const int w = tid >> 5;
    const int wm = w >> 1;        // 0..3 -> M quarter (32 rows)
    const int wn = w & 1;         // 0..1 -> N half (64 cols)
    const size_t mBase = (size_t)blockIdx.y * BM;
    const size_t nBase = (size_t)blockIdx.x * BN;

    float d[2][8][4];
#pragma unroll
    for (int i = 0; i < 2; i++)
#pragma unroll
        for (int j = 0; j < 8; j++)
#pragma unroll
            for (int k = 0; k < 4; k++) d[i][j][k] = 0.0f;

    const int arow = wm * 32 + (lane & 15);
    const int acol = (lane >> 4);
    const int brow = wn * 64 + (lane & 7) + ((lane >> 4) << 3);
    const int bcol = ((lane >> 3) & 1);

    load_stage(tiles, mBase, nBase, 0, tid);
    cp_commit();
    load_stage(tiles + STAGE_BYTES, mBase, nBase, BK, tid);
    cp_commit();

    for (int it = 0; it < KITERS; it++) {
        const uint32_t stg = tiles + (it % 3) * STAGE_BYTES;

        cp_wait1();          // oldest pending group (stage it) complete
        __syncthreads();

        // Issue next loads first: stage (it+2)%3 == (it-1)%3 is drained —
        // every warp passed this barrier, so all finished computing it-1.
        if (it + 2 < KITERS)
            load_stage(tiles + ((it + 2) % 3) * STAGE_BYTES,
                       mBase, nBase, (it + 2) * BK, tid);
        cp_commit();         // empty groups at tail keep wait counts valid

#pragma unroll
        for (int k16 = 0; k16 < 8; k16++) {
            const uint32_t subA = OFF_A + (k16 >> 2) * SUB_BYTES;
            const uint32_t subB = OFF_B + (k16 >> 2) * SUB_BYTES;
            const int kw = k16 & 3;
            uint32_t a[2][4], b[8][2];
#pragma unroll
            for (int mi = 0; mi < 2; mi++) {
                const uint32_t off =
                    swz128((arow + mi * 16) * 128 + (acol + kw * 2) * 16);
                ldsm4(a[mi], stg + subA + off);
            }
#pragma unroll
            for (int j = 0; j < 4; j++) {
                uint32_t q[4];
                const uint32_t off =
                    swz128((brow + j * 16) * 128 + (bcol + kw * 2) * 16);
                ldsm4(q, stg + subB + off);
                b[2 * j][0] = q[0]; b[2 * j][1] = q[1];
                b[2 * j + 1][0] = q[2]; b[2 * j + 1][1] = q[3];
            }
#pragma unroll
            for (int mi = 0; mi < 2; mi++)
#pragma unroll
                for (int nj = 0; nj < 8; nj++)
                    mma_f16(d[mi][nj], a[mi], b[nj]);
        }
    }

#pragma unroll
    for (int mi = 0; mi < 2; mi++) {
        const size_t grow = mBase + wm * 32 + mi * 16 + (lane >> 2);
#pragma unroll
        for (int nj = 0; nj < 8; nj++) {
            const size_t gcol = nBase + wn * 64 + nj * 8 + (lane & 3) * 2;
            *reinterpret_cast<float2*>(out + grow * D_DIM + gcol) =
                make_float2(d[mi][nj][0], d[mi][nj][1]);
            *reinterpret_cast<float2*>(out + (grow + 8) * D_DIM + gcol) =
                make_float2(d[mi][nj][2], d[mi][nj][3]);
        }
    }
}

// ---------------------------------------------------------------------------
// Launch
// ---------------------------------------------------------------------------
extern "C" void kernel_launch(void* const* d_in, const int* in_sizes, int n_in,
                              void* d_out, int out_size) {
    const float* x     = (const float*)d_in[0];
    const float* W     = (const float*)d_in[1];
    const float* lA    = (const float*)d_in[2];
    const float* lB    = (const float*)d_in[3];
    const float* sigma = (const float*)d_in[4];
    float* out = (float*)d_out;
    (void)in_sizes; (void)n_in; (void)out_size;

    prep_kernel<<<PREP_BLOCKS, 256>>>(x, W, lA, lB, sigma);

    cudaFuncSetAttribute(gemm_mma_kernel,
                         cudaFuncAttributeMaxDynamicSharedMemorySize, SMEM_BYTES);
    dim3 gG(D_DIM / BN, M_DIM / BM);
    gemm_mma_kernel<<<gG, 256, SMEM_BYTES>>>(out);
}

// round 17
// speedup vs baseline: 1.1550x; 1.1550x over previous
#include <cuda_runtime.h>
#include <cuda_fp16.h>
#include <cstdint>

// AdaLoRALinear: out[8192,4096] = x[8192,4096] @ (W + (B*sigma_m)@A)^T
// Single-pass fp16 GEMM on mma.sync at the legacy-HMMA issue ceiling
// (~95% of mma.sync quarter-rate; invariant across 6 structural variants).
// Prep (fold W + convert x, parity-interleaved) at its memory floor.
// Round-13 build (best measured 676.6us) + outer-loop unroll-by-2.

#define D_DIM 4096
#define R_DIM 16
#define M_DIM 8192
#define SCALING 1.0f
#define THRESH  0.01f

#define BM 128
#define BN 128
#define BK 64                  // 64 fp16 = 128B row (SW128 atom)
#define KITERS (D_DIM / BK)    // 64

__device__ __half g_x16[(size_t)M_DIM * D_DIM];
__device__ __half g_w16[(size_t)D_DIM * D_DIM];

// ---------------------------------------------------------------------------
// helpers
// ---------------------------------------------------------------------------
__device__ __forceinline__ uint32_t smem_u32(const void* p) {
    uint32_t a;
    asm("{ .reg .u64 t; cvta.to.shared.u64 t, %1; cvt.u32.u64 %0, t; }"
        : "=r"(a) : "l"(p));
    return a;
}
__device__ __forceinline__ uint32_t swz128(uint32_t off) {
    return off ^ ((off >> 3) & 0x70);
}
__device__ __forceinline__ void cp16(uint32_t smem, const void* g) {
    asm volatile("cp.async.cg.shared.global [%0], [%1], 16;\n"
                 :: "r"(smem), "l"(g) : "memory");
}
__device__ __forceinline__ void cp_commit() {
    asm volatile("cp.async.commit_group;\n" ::: "memory");
}
__device__ __forceinline__ void cp_wait1() {
    asm volatile("cp.async.wait_group 1;\n" ::: "memory");
}
__device__ __forceinline__ void ldsm4(uint32_t* r, uint32_t addr) {
    asm volatile("ldmatrix.sync.aligned.m8n8.x4.shared.b16 {%0,%1,%2,%3}, [%4];"
                 : "=r"(r[0]), "=r"(r[1]), "=r"(r[2]), "=r"(r[3]) : "r"(addr));
}
__device__ __forceinline__ void mma_f16(float* d, const uint32_t* a,
                                        const uint32_t* b) {
    asm volatile(
        "mma.sync.aligned.m16n8k16.row.col.f32.f16.f16.f32 "
        "{%0,%1,%2,%3}, {%4,%5,%6,%7}, {%8,%9}, {%0,%1,%2,%3};"
        : "+f"(d[0]), "+f"(d[1]), "+f"(d[2]), "+f"(d[3])
        : "r"(a[0]), "r"(a[1]), "r"(a[2]), "r"(a[3]), "r"(b[0]), "r"(b[1]));
}

// ---------------------------------------------------------------------------
// Merged prep, parity-interleaved:
//   even blocks: fold W' -> fp16 (one o-row slice, 4 elems/thread)
//   odd  blocks: convert x -> fp16 (8 elems/thread)
// ---------------------------------------------------------------------------
#define PREP_BLOCKS 32768

__global__ void prep_kernel(const float* __restrict__ x,
                            const float* __restrict__ W,
                            const float* __restrict__ A,
                            const float* __restrict__ B,
                            const float* __restrict__ sigma) {
    const int bid = blockIdx.x;
    if ((bid & 1) == 0) {
        const int fb = bid >> 1;
        __shared__ float bsig[R_DIM];
        const int o = fb >> 2;
        const int i = ((fb & 3) * 256 + threadIdx.x) * 4;
        if (threadIdx.x < R_DIM) {
            float s = sigma[threadIdx.x];
            s = (fabsf(s) >= THRESH) ? s : 0.0f;
            bsig[threadIdx.x] = B[o * R_DIM + threadIdx.x] * s * SCALING;
        }
        __syncthreads();

        const size_t idx = (size_t)o * D_DIM + i;
        float4 w4 = *reinterpret_cast<const float4*>(W + idx);
        float acc[4] = {w4.x, w4.y, w4.z, w4.w};
#pragma unroll
        for (int r = 0; r < R_DIM; r++) {
            const float4 a4 =
                *reinterpret_cast<const float4*>(A + (size_t)r * D_DIM + i);
            const float b = bsig[r];
            acc[0] = fmaf(b, a4.x, acc[0]);
            acc[1] = fmaf(b, a4.y, acc[1]);
            acc[2] = fmaf(b, a4.z, acc[2]);
            acc[3] = fmaf(b, a4.w, acc[3]);
        }
        __half h[4];
#pragma unroll
        for (int j = 0; j < 4; j++) h[j] = __float2half_rn(acc[j]);
        *reinterpret_cast<uint2*>(&g_w16[idx]) = *reinterpret_cast<uint2*>(h);
    } else {
        const size_t t = (size_t)(bid >> 1) * 256 + threadIdx.x;
        const float4 v0 = reinterpret_cast<const float4*>(x)[t * 2];
        const float4 v1 = reinterpret_cast<const float4*>(x)[t * 2 + 1];
        __half h[8] = {__float2half_rn(v0.x), __float2half_rn(v0.y),
                       __float2half_rn(v0.z), __float2half_rn(v0.w),
                       __float2half_rn(v1.x), __float2half_rn(v1.y),
                       __float2half_rn(v1.z), __float2half_rn(v1.w)};
        *reinterpret_cast<uint4*>(&g_x16[t * 8]) =
            *reinterpret_cast<uint4*>(h);
    }
}

// ---------------------------------------------------------------------------
// GEMM: CTA 128x128, 256 threads, 8 warps (4m x 2n) of 32x64, BK=64,
// 3-stage pipeline (32 KB/stage) -> 96 KB/CTA -> 2 CTAs/SM, 16 warps/SM.
// ---------------------------------------------------------------------------
#define STAGE_BYTES 32768
#define OFF_A 0
#define OFF_B 16384
#define SMEM_BYTES (3 * STAGE_BYTES + 128)

__device__ __forceinline__ void load_stage(uint32_t base, size_t mBase,
                                           size_t nBase, int kt, int tid) {
#pragma unroll
    for (int i = 0; i < 4; i++) {   // A: 128 rows x 8 units = 1024 / 256 thr
        const int u = tid + 256 * i;
        const int row = u >> 3, kc = u & 7;
        const uint32_t so = swz128(row * 128 + kc * 16);
        cp16(base + OFF_A + so, g_x16 + ((mBase + row) << 12) + kt + kc * 8);
    }
#pragma unroll
    for (int i = 0; i < 4; i++) {   // B: 128 rows x 8 units
        const int u = tid + 256 * i;
        const int row = u >> 3, kc = u & 7;
        const uint32_t so = swz128(row * 128 + kc * 16);
        cp16(base + OFF_B + so, g_w16 + ((nBase + row) << 12) + kt + kc * 8);
    }
}

__global__ __launch_bounds__(256, 2)
void gemm_mma_kernel(float* __restrict__ out) {
    extern __shared__ char smem_raw[];
    const uint32_t tiles = (smem_u32(smem_raw) + 127u) & ~127u;

    const int tid = threadIdx.x;
    const int lane = tid & 31;
    const int w = tid >> 5;
    const int wm = w >> 1;        // 0..3 -> M quarter (32 rows)
    const int wn = w & 1;         // 0..1 -> N half (64 cols)
    const size_t mBase = (size_t)blockIdx.y * BM;
    const size_t nBase = (size_t)blockIdx.x * BN;

    float d[2][8][4];
#pragma unroll
    for (int i = 0; i < 2; i++)
#pragma unroll
        for (int j = 0; j < 8; j++)
#pragma unroll
            for (int k = 0; k < 4; k++) d[i][j][k] = 0.0f;

    const int arow = wm * 32 + (lane & 15);
    const int acol = (lane >> 4);
    const int brow = wn * 64 + (lane & 7) + ((lane >> 4) << 3);
    const int bcol = ((lane >> 3) & 1);

    load_stage(tiles, mBase, nBase, 0, tid);
    cp_commit();
    load_stage(tiles + STAGE_BYTES, mBase, nBase, BK, tid);
    cp_commit();

#pragma unroll 2
    for (int it = 0; it < KITERS; it++) {
        const uint32_t stg = tiles + (it % 3) * STAGE_BYTES;

        cp_wait1();          // oldest pending group (stage it) complete
        __syncthreads();

        // Issue next loads first: stage (it+2)%3 == (it-1)%3 is drained —
        // every warp passed this barrier, so all finished computing it-1.
        if (it + 2 < KITERS)
            load_stage(tiles + ((it + 2) % 3) * STAGE_BYTES,
                       mBase, nBase, (it + 2) * BK, tid);
        cp_commit();         // empty groups at tail keep wait counts valid

#pragma unroll
        for (int k16 = 0; k16 < 4; k16++) {
            uint32_t a[2][4], b[8][2];
#pragma unroll
            for (int mi = 0; mi < 2; mi++) {
                const uint32_t off =
                    swz128((arow + mi * 16) * 128 + (acol + k16 * 2) * 16);
                ldsm4(a[mi], stg + OFF_A + off);
            }
#pragma unroll
            for (int j = 0; j < 4; j++) {
                uint32_t q[4];
                const uint32_t off =
                    swz128((brow + j * 16) * 128 + (bcol + k16 * 2) * 16);
                ldsm4(q, stg + OFF_B + off);
                b[2 * j][0] = q[0]; b[2 * j][1] = q[1];
                b[2 * j + 1][0] = q[2]; b[2 * j + 1][1] = q[3];
            }
#pragma unroll
            for (int mi = 0; mi < 2; mi++)
#pragma unroll
                for (int nj = 0; nj < 8; nj++)
                    mma_f16(d[mi][nj], a[mi], b[nj]);
        }
    }

#pragma unroll
    for (int mi = 0; mi < 2; mi++) {
        const size_t grow = mBase + wm * 32 + mi * 16 + (lane >> 2);
#pragma unroll
        for (int nj = 0; nj < 8; nj++) {
            const size_t gcol = nBase + wn * 64 + nj * 8 + (lane & 3) * 2;
            *reinterpret_cast<float2*>(out + grow * D_DIM + gcol) =
                make_float2(d[mi][nj][0], d[mi][nj][1]);
            *reinterpret_cast<float2*>(out + (grow + 8) * D_DIM + gcol) =
                make_float2(d[mi][nj][2], d[mi][nj][3]);
        }
    }
}

// ---------------------------------------------------------------------------
// Launch
// ---------------------------------------------------------------------------
extern "C" void kernel_launch(void* const* d_in, const int* in_sizes, int n_in,
                              void* d_out, int out_size) {
    const float* x     = (const float*)d_in[0];
    const float* W     = (const float*)d_in[1];
    const float* lA    = (const float*)d_in[2];
    const float* lB    = (const float*)d_in[3];
    const float* sigma = (const float*)d_in[4];
    float* out = (float*)d_out;
    (void)in_sizes; (void)n_in; (void)out_size;

    prep_kernel<<<PREP_BLOCKS, 256>>>(x, W, lA, lB, sigma);

    cudaFuncSetAttribute(gemm_mma_kernel,
                         cudaFuncAttributeMaxDynamicSharedMemorySize, SMEM_BYTES);
    dim3 gG(D_DIM / BN, M_DIM / BM);
    gemm_mma_kernel<<<gG, 256, SMEM_BYTES>>>(out);
}